// round 9
// baseline (speedup 1.0000x reference)
#include <cuda_runtime.h>
#include <math.h>

struct Params {
    float beta[18];
    unsigned fk0[16];
    unsigned fk1[16];
};

// -------- device scratch (allocation-free, module statics) --------
__device__ float g_M[4096];          // W_dec W_dec^T
__device__ float g_mu[8192];         // [b][d]
__device__ float g_xWt[8192];        // [b][d] x W_dec^T
__device__ float g_V[4096];          // eigenvectors [d][i]
__device__ float g_lam[64];          // eigenvalues
__device__ float g_mtT[8192];        // [i][b]  mu~
__device__ float g_xtT[8192];        // [i][b]  xWt~
__device__ float g_uT[8192];         // [i][b]  u~ = xWt~ - mu~
__device__ float g_cw[128];          // const_b
__device__ float g_pc[1024];         // [k][i] p coefficient
__device__ float g_qd[1024];         // [k][i] noise coefficient (sqrt2 folded)
__device__ float g_dT[16 * 8192];    // [k][i][b] drift
__device__ float g_epst[134217728];  // [k][chain][i] qd*eps~ + d~  (512MB)
__device__ float g_slw[131072];      // [b][n]

// ---------------------------------------------------------------------------
// threefry2x32 — exact JAX schedule (host-usable generic version)
// ---------------------------------------------------------------------------
__host__ __device__ __forceinline__ void tf2x32(unsigned k0, unsigned k1,
                                                unsigned x0, unsigned x1,
                                                unsigned* o0, unsigned* o1) {
    unsigned k2 = k0 ^ k1 ^ 0x1BD11BDAu;
    x0 += k0; x1 += k1;
#define TFR(r) { x0 += x1; x1 = (x1 << (r)) | (x1 >> (32 - (r))); x1 ^= x0; }
    TFR(13) TFR(15) TFR(26) TFR(6)
    x0 += k1; x1 += k2 + 1u;
    TFR(17) TFR(29) TFR(16) TFR(24)
    x0 += k2; x1 += k0 + 2u;
    TFR(13) TFR(15) TFR(26) TFR(6)
    x0 += k0; x1 += k1 + 3u;
    TFR(17) TFR(29) TFR(16) TFR(24)
    x0 += k1; x1 += k2 + 4u;
    TFR(13) TFR(15) TFR(26) TFR(6)
    x0 += k2; x1 += k0 + 5u;
#undef TFR
    *o0 = x0; *o1 = x1;
}

// XLA ErfInv32 (Giles): branch-free, both polynomials + select.
__device__ __forceinline__ float xla_erfinv(float x) {
    float w = -__logf(fmaf(x, -x, 1.0f));     // -log(1 - x^2)
    float wc = w - 2.5f;
    float p1 = 2.81022636e-08f;
    p1 = fmaf(p1, wc, 3.43273939e-07f);
    p1 = fmaf(p1, wc, -3.5233877e-06f);
    p1 = fmaf(p1, wc, -4.39150654e-06f);
    p1 = fmaf(p1, wc, 0.00021858087f);
    p1 = fmaf(p1, wc, -0.00125372503f);
    p1 = fmaf(p1, wc, -0.00417768164f);
    p1 = fmaf(p1, wc, 0.246640727f);
    p1 = fmaf(p1, wc, 1.50140941f);
    float wt = sqrtf(w) - 3.0f;
    float p2 = -0.000200214257f;
    p2 = fmaf(p2, wt, 0.000100950558f);
    p2 = fmaf(p2, wt, 0.00134934322f);
    p2 = fmaf(p2, wt, -0.00367342844f);
    p2 = fmaf(p2, wt, 0.00573950773f);
    p2 = fmaf(p2, wt, -0.0076224613f);
    p2 = fmaf(p2, wt, 0.00943887047f);
    p2 = fmaf(p2, wt, 1.00167406f);
    p2 = fmaf(p2, wt, 2.83297682f);
    float p = (w < 5.0f) ? p1 : p2;
    return p * x;
}

// partitionable-mode draw: bits = out0 ^ out1 of cipher(key, (0, idx)).
// Returns erfinv(u); sqrt(2) folded into g_qd.
__device__ __forceinline__ float draw_erfinv(unsigned k0, unsigned k1, unsigned k2,
                                             unsigned idx) {
    unsigned x0 = k0, x1 = idx + k1;
#define TFR(r) { x0 += x1; x1 = (x1 << (r)) | (x1 >> (32 - (r))); x1 ^= x0; }
    TFR(13) TFR(15) TFR(26) TFR(6)
    x0 += k1; x1 += k2 + 1u;
    TFR(17) TFR(29) TFR(16) TFR(24)
    x0 += k2; x1 += k0 + 2u;
    TFR(13) TFR(15) TFR(26) TFR(6)
    x0 += k0; x1 += k1 + 3u;
    TFR(17) TFR(29) TFR(16) TFR(24)
    x0 += k1; x1 += k2 + 4u;
    TFR(13) TFR(15) TFR(26) TFR(6)
    x0 += k2; x1 += k0 + 5u;
#undef TFR
    unsigned bits = x0 ^ x1;
    float f = __uint_as_float((bits >> 9) | 0x3f800000u) - 1.0f;  // [0,1)
    const float lo = -0.99999994f;                  // nextafterf(-1,0)
    float v = fmaf(f, 2.0f, lo);                    // (1 - lo) rounds to 2.0f
    return xla_erfinv(v);
}

// -------- packed f32x2 helpers --------
__device__ __forceinline__ unsigned long long pack2(float a, float b) {
    unsigned long long r;
    asm("mov.b64 %0, {%1, %2};" : "=l"(r) : "f"(a), "f"(b));
    return r;
}
__device__ __forceinline__ void unpack2(unsigned long long v, float& a, float& b) {
    asm("mov.b64 {%0, %1}, %2;" : "=f"(a), "=f"(b) : "l"(v));
}
#define FMA2(c, a, bb) asm("fma.rn.f32x2 %0, %1, %2, %0;" : "+l"(c) : "l"(a), "l"(bb))

// ---------------------------------------------------------------------------
// launch 1: M, mu, xWt
// ---------------------------------------------------------------------------
__global__ void k_setup1(const float* __restrict__ x,
                         const float* __restrict__ We,
                         const float* __restrict__ Wd) {
    int idx = blockIdx.x * 256 + threadIdx.x;
    if (idx < 4096) {
        int i = idx >> 6, j = idx & 63;
        float s = 0.f;
        for (int e = 0; e < 64; e++) s = fmaf(Wd[i * 64 + e], Wd[j * 64 + e], s);
        g_M[idx] = s;
    } else if (idx < 12288) {
        int o = idx - 4096; int b = o >> 6, d = o & 63;
        float sm = 0.f, sw = 0.f;
        for (int e = 0; e < 64; e++) {
            float xe = x[b * 64 + e];
            sm = fmaf(xe, We[e * 64 + d], sm);
            sw = fmaf(xe, Wd[d * 64 + e], sw);
        }
        g_mu[o] = sm; g_xWt[o] = sw;
    }
}

// ---------------------------------------------------------------------------
// launch 2: Jacobi eigensolver (7 sweeps) + cw computation at the end
// ---------------------------------------------------------------------------
__global__ void __launch_bounds__(1024) k_jac_cw(const float* __restrict__ x) {
    __shared__ float A[64][65];
    __shared__ float Vv[64][65];
    __shared__ float cs[32], sn[32];
    __shared__ int pp[32], qq[32];
    const int t = threadIdx.x;
    for (int o = t; o < 4096; o += 1024) {
        int i = o >> 6, j = o & 63;
        A[i][j] = g_M[o];
        Vv[i][j] = (i == j) ? 1.f : 0.f;
    }
    __syncthreads();
    for (int sweep = 0; sweep < 7; sweep++) {
        for (int r = 0; r < 63; r++) {
            if (t < 32) {
                int p, q;
                if (t == 0) { p = 63; q = r; }
                else { p = (r + t) % 63; q = (r - t + 63) % 63; }
                if (p > q) { int tmp = p; p = q; q = tmp; }
                pp[t] = p; qq[t] = q;
                float apq = A[p][q], app = A[p][p], aqq = A[q][q];
                float c = 1.f, s = 0.f;
                if (fabsf(apq) > 1e-30f) {
                    float tau = (aqq - app) / (2.f * apq);
                    float tt = ((tau >= 0.f) ? 1.f : -1.f) /
                               (fabsf(tau) + sqrtf(1.f + tau * tau));
                    c = rsqrtf(1.f + tt * tt);
                    s = tt * c;
                }
                cs[t] = c; sn[t] = s;
            }
            __syncthreads();
            for (int u = t; u < 2048; u += 1024) {
                int m = u >> 6, j = u & 63;
                int p = pp[m], q = qq[m];
                float c = cs[m], s = sn[m];
                float ap = A[p][j], aq = A[q][j];
                A[p][j] = c * ap - s * aq;
                A[q][j] = s * ap + c * aq;
            }
            __syncthreads();
            for (int u = t; u < 2048; u += 1024) {
                int m = u >> 6, i = u & 63;
                int p = pp[m], q = qq[m];
                float c = cs[m], s = sn[m];
                float ap = A[i][p], aq = A[i][q];
                A[i][p] = c * ap - s * aq;
                A[i][q] = s * ap + c * aq;
                float vp = Vv[i][p], vq = Vv[i][q];
                Vv[i][p] = c * vp - s * vq;
                Vv[i][q] = s * vp + c * vq;
            }
            __syncthreads();
        }
    }
    for (int o = t; o < 4096; o += 1024) g_V[o] = Vv[o >> 6][o & 63];
    if (t < 64) g_lam[t] = A[t][t];
    if (t < 128) {   // const_b = 0.5||mu||^2 - 0.5||x||^2 - 32 log 2pi
        float s = 0.f, sx = 0.f;
        for (int d = 0; d < 64; d++) {
            float m = g_mu[t * 64 + d]; s = fmaf(m, m, s);
            float xe = x[t * 64 + d];   sx = fmaf(xe, xe, sx);
        }
        g_cw[t] = 0.5f * s - 0.5f * sx - 58.81206612509905f;
    }
}

// ---------------------------------------------------------------------------
// launch 3: eigenbasis transform + per-step coefficients + drift, fused
// ---------------------------------------------------------------------------
__global__ void k_transcoef(Params prm) {
    int o = blockIdx.x * 256 + threadIdx.x;   // 8192 = (b, i)
    int b = o >> 6, i = o & 63;
    float sm = 0.f, sx = 0.f;
    for (int d = 0; d < 64; d++) {
        float v = g_V[d * 64 + i];
        sm = fmaf(g_mu[b * 64 + d], v, sm);
        sx = fmaf(g_xWt[b * 64 + d], v, sx);
    }
    g_mtT[i * 128 + b] = sm;
    g_xtT[i * 128 + b] = sx;
    g_uT[i * 128 + b] = sx - sm;
    const float h = 0.05f, h2 = 0.0025f;
    float lam = g_lam[i];
    for (int k = 0; k < 16; k++) {
        float bk = prm.beta[k + 1];
        float c = h2 * (bk * lam + 1.f);
        float sd = h2 * (4.5f - 3.f * c + 0.5f * c * c);
        float vt = bk * sx + (1.f - bk) * sm;
        g_dT[(k * 64 + i) * 128 + b] = sd * vt;
        if (b == 0) {
            g_pc[k * 64 + i] = 1.f - 4.5f * c + 3.f * c * c - 0.5f * c * c * c;
            g_qd[k * 64 + i] = 1.41421356237f * h * (3.f - 4.f * c + c * c);
        }
    }
}

// ---------------------------------------------------------------------------
// launch 4: k_eps — stateless over (chain, step). Draw 64 erfinv values,
// multiply by sVq = V * qd(k), add drift, store g_epst[k][chain][i].
// ---------------------------------------------------------------------------
__global__ void __launch_bounds__(128) k_eps(Params prm) {
    __shared__ float sVq[4096];               // [d][i] = V[d][i] * qd[k][i]
    const int k  = blockIdx.x >> 10;
    const int cb = blockIdx.x & 1023;
    const int t  = threadIdx.x;
    const unsigned chain = (unsigned)cb * 128u + (unsigned)t;
    for (int o = t; o < 4096; o += 128)
        sVq[o] = g_V[o] * g_qd[k * 64 + (o & 63)];
    __syncthreads();

    const unsigned fk0 = prm.fk0[k], fk1 = prm.fk1[k];
    const unsigned fk2 = fk0 ^ fk1 ^ 0x1BD11BDAu;
    const unsigned base = chain * 64u;
    unsigned long long acc[32];
#pragma unroll
    for (int j = 0; j < 32; j++) acc[j] = 0ull;

#pragma unroll 4
    for (int d = 0; d < 64; d++) {
        float e = draw_erfinv(fk0, fk1, fk2, base + (unsigned)d);
        unsigned long long pe = pack2(e, e);
        const ulonglong2* row = (const ulonglong2*)(sVq + d * 64);
#pragma unroll
        for (int j = 0; j < 16; j++) {
            ulonglong2 w = row[j];
            FMA2(acc[2 * j],     pe, w.x);
            FMA2(acc[2 * j + 1], pe, w.y);
        }
    }
    const float* dTk = g_dT + k * 8192 + t;             // + i*128
    float4* op = (float4*)(g_epst + (((size_t)k) << 23) + (size_t)chain * 64u);
#pragma unroll
    for (int j = 0; j < 16; j++) {
        float a0, a1, a2, a3;
        unpack2(acc[2 * j],     a0, a1);
        unpack2(acc[2 * j + 1], a2, a3);
        a0 += dTk[(4 * j + 0) * 128];
        a1 += dTk[(4 * j + 1) * 128];
        a2 += dTk[(4 * j + 2) * 128];
        a3 += dTk[(4 * j + 3) * 128];
        op[j] = make_float4(a0, a1, a2, a3);
    }
}

// ---------------------------------------------------------------------------
// launch 5: k_main — per-chain elementwise recursion + weights.
// 128 threads/block: b == t, n == blockIdx.x.
// dyn smem: sU 8192 | sV 4096 | sPc 1024 | sLam 64  (53504 B)
// ---------------------------------------------------------------------------
__global__ void __launch_bounds__(128) k_main(const float* __restrict__ qn,
                                              Params prm) {
    extern __shared__ float dsm[];
    float* sU   = dsm;
    float* sV   = dsm + 8192;
    float* sPc  = dsm + 12288;
    float* sLam = dsm + 13312;
    const int t = threadIdx.x;
    const unsigned chain = (unsigned)blockIdx.x * 128u + (unsigned)t;
    const int b = t;
    const int n = blockIdx.x;

    for (int o = t; o < 8192; o += 128) sU[o] = g_uT[o];
    for (int o = t; o < 4096; o += 128) sV[o] = g_V[o];
    for (int o = t; o < 1024; o += 128) sPc[o] = g_pc[o];
    if (t < 64) sLam[t] = g_lam[t];
    __syncthreads();

    // q~0 = mu~ + (qn V)
    float qreg[64];
    const float4* qp = (const float4*)(qn + (size_t)chain * 64u);
#pragma unroll
    for (int j = 0; j < 16; j++) {
        float4 v = qp[j];
        qreg[4 * j] = v.x; qreg[4 * j + 1] = v.y;
        qreg[4 * j + 2] = v.z; qreg[4 * j + 3] = v.w;
    }
    unsigned long long acc[32];
#pragma unroll
    for (int j = 0; j < 32; j++) acc[j] = 0ull;
#pragma unroll 4
    for (int d = 0; d < 64; d++) {
        unsigned long long pe = pack2(qreg[d], qreg[d]);
        const ulonglong2* row = (const ulonglong2*)(sV + d * 64);
#pragma unroll
        for (int j = 0; j < 16; j++) {
            ulonglong2 w = row[j];
            FMA2(acc[2 * j],     pe, w.x);
            FMA2(acc[2 * j + 1], pe, w.y);
        }
    }
    float q[64];
#pragma unroll
    for (int j = 0; j < 32; j++) {
        float a0, a1;
        unpack2(acc[j], a0, a1);
        q[2 * j]     = a0 + g_mtT[(2 * j) * 128 + b];
        q[2 * j + 1] = a1 + g_mtT[(2 * j + 1) * 128 + b];
    }

    const float cw = g_cw[b];
    float slw;
    {
        float dot = 0.f, qsq = 0.f;
#pragma unroll
        for (int i = 0; i < 64; i++) {
            dot = fmaf(q[i], sU[i * 128 + b], dot);
            qsq = fmaf(sLam[i] * q[i], q[i], qsq);
        }
        float w = cw + dot - 0.5f * qsq;
        slw = (prm.beta[1] - prm.beta[0]) * w;
    }

    for (int k = 0; k < 16; k++) {
        const float4* ep = (const float4*)(g_epst + (((size_t)k) << 23) +
                                           (size_t)chain * 64u);
#pragma unroll
        for (int j = 0; j < 16; j++) {
            float4 e = __ldg(ep + j);
            q[4 * j]     = fmaf(sPc[k * 64 + 4 * j],     q[4 * j],     e.x);
            q[4 * j + 1] = fmaf(sPc[k * 64 + 4 * j + 1], q[4 * j + 1], e.y);
            q[4 * j + 2] = fmaf(sPc[k * 64 + 4 * j + 2], q[4 * j + 2], e.z);
            q[4 * j + 3] = fmaf(sPc[k * 64 + 4 * j + 3], q[4 * j + 3], e.w);
        }
        float dot = 0.f, qsq = 0.f;
#pragma unroll
        for (int i = 0; i < 64; i++) {
            dot = fmaf(q[i], sU[i * 128 + b], dot);
            qsq = fmaf(sLam[i] * q[i], q[i], qsq);
        }
        float w = cw + dot - 0.5f * qsq;
        slw = fmaf(prm.beta[k + 2] - prm.beta[k + 1], w, slw);
    }
    g_slw[b * 1024 + n] = slw;
}

// ---------------------------------------------------------------------------
// launch 6: logsumexp over n, minus log(1024)
// ---------------------------------------------------------------------------
__global__ void k_reduce(float* __restrict__ out) {
    const int b = blockIdx.x;
    const int t = threadIdx.x;          // 128
    __shared__ float red[128];
    float m = -3.4e38f;
    for (int i = t; i < 1024; i += 128) m = fmaxf(m, g_slw[b * 1024 + i]);
    red[t] = m; __syncthreads();
    for (int s = 64; s > 0; s >>= 1) {
        if (t < s) red[t] = fmaxf(red[t], red[t + s]);
        __syncthreads();
    }
    float mx = red[0]; __syncthreads();
    float acc = 0.f;
    for (int i = t; i < 1024; i += 128) acc += expf(g_slw[b * 1024 + i] - mx);
    red[t] = acc; __syncthreads();
    for (int s = 64; s > 0; s >>= 1) {
        if (t < s) red[t] += red[t + s];
        __syncthreads();
    }
    if (t == 0) out[b] = mx + logf(red[0]) - 6.9314718055994531f;  // log(1024)
}

// ---------------------------------------------------------------------------
extern "C" void kernel_launch(void* const* d_in, const int* in_sizes, int n_in,
                              void* d_out, int out_size) {
    const float* x    = (const float*)d_in[0];
    const float* Wenc = (const float*)d_in[1];
    const float* Wdec = (const float*)d_in[2];
    const float* qn   = (const float*)d_in[3];
    // d_in[4] = p_noise — unused (momentum fully resampled each step)
    float* out = (float*)d_out;

    Params prm;
    double bb[18];
    for (int i = 0; i < 18; i++) {
        double z = 4.0 * (2.0 * ((double)i / 17.0) - 1.0);
        bb[i] = 1.0 / (1.0 + exp(-z));
    }
    for (int i = 0; i < 18; i++)
        prm.beta[i] = (float)((bb[i] - bb[0]) / (bb[17] - bb[0]));
    for (int k = 1; k <= 16; k++) {
        unsigned o0, o1;
        tf2x32(0u, 42u, 0u, (unsigned)k, &o0, &o1);   // fold_in(key(42), k)
        prm.fk0[k - 1] = o0; prm.fk1[k - 1] = o1;
    }

    cudaFuncSetAttribute(k_main, cudaFuncAttributeMaxDynamicSharedMemorySize, 53504);

    k_setup1<<<48, 256>>>(x, Wenc, Wdec);
    k_jac_cw<<<1, 1024>>>(x);
    k_transcoef<<<32, 256>>>(prm);
    k_eps<<<16384, 128>>>(prm);
    k_main<<<1024, 128, 53504>>>(qn, prm);
    k_reduce<<<128, 128>>>(out);
}

// round 10
// speedup vs baseline: 1.0958x; 1.0958x over previous
#include <cuda_runtime.h>
#include <math.h>

struct Params {
    float beta[18];
    unsigned fk0[16];
    unsigned fk1[16];
};

// -------- device scratch (allocation-free, module statics) --------
__device__ float g_M[4096];          // W_dec W_dec^T
__device__ float g_mu[8192];         // [b][d]
__device__ float g_xWt[8192];        // [b][d] x W_dec^T
__device__ float g_V[4096];          // eigenvectors [d][i]
__device__ float g_lam[64];          // eigenvalues
__device__ float g_mtT[8192];        // [i][b]  mu~
__device__ float g_uT[8192];         // [i][b]  u~ = xWt~ - mu~
__device__ float g_cw[128];          // const_b
__device__ float g_pc[1024];         // [k][i] p coefficient
__device__ float g_qd[1024];         // [k][i] noise coefficient (sqrt2 folded)
__device__ float g_dT[16 * 8192];    // [k][i][b] drift
__device__ unsigned long long g_eps2[67108864];  // [k*32+j][chain] pair (512MB)
__device__ float g_slw[131072];      // [b][n]

// ---------------------------------------------------------------------------
// threefry2x32 — exact JAX schedule (host-usable generic version)
// ---------------------------------------------------------------------------
__host__ __device__ __forceinline__ void tf2x32(unsigned k0, unsigned k1,
                                                unsigned x0, unsigned x1,
                                                unsigned* o0, unsigned* o1) {
    unsigned k2 = k0 ^ k1 ^ 0x1BD11BDAu;
    x0 += k0; x1 += k1;
#define TFR(r) { x0 += x1; x1 = (x1 << (r)) | (x1 >> (32 - (r))); x1 ^= x0; }
    TFR(13) TFR(15) TFR(26) TFR(6)
    x0 += k1; x1 += k2 + 1u;
    TFR(17) TFR(29) TFR(16) TFR(24)
    x0 += k2; x1 += k0 + 2u;
    TFR(13) TFR(15) TFR(26) TFR(6)
    x0 += k0; x1 += k1 + 3u;
    TFR(17) TFR(29) TFR(16) TFR(24)
    x0 += k1; x1 += k2 + 4u;
    TFR(13) TFR(15) TFR(26) TFR(6)
    x0 += k2; x1 += k0 + 5u;
#undef TFR
    *o0 = x0; *o1 = x1;
}

// XLA ErfInv32 (Giles): branch-free, both polynomials + select.
__device__ __forceinline__ float xla_erfinv(float x) {
    float w = -__logf(fmaf(x, -x, 1.0f));     // -log(1 - x^2)
    float wc = w - 2.5f;
    float p1 = 2.81022636e-08f;
    p1 = fmaf(p1, wc, 3.43273939e-07f);
    p1 = fmaf(p1, wc, -3.5233877e-06f);
    p1 = fmaf(p1, wc, -4.39150654e-06f);
    p1 = fmaf(p1, wc, 0.00021858087f);
    p1 = fmaf(p1, wc, -0.00125372503f);
    p1 = fmaf(p1, wc, -0.00417768164f);
    p1 = fmaf(p1, wc, 0.246640727f);
    p1 = fmaf(p1, wc, 1.50140941f);
    float wt = sqrtf(w) - 3.0f;
    float p2 = -0.000200214257f;
    p2 = fmaf(p2, wt, 0.000100950558f);
    p2 = fmaf(p2, wt, 0.00134934322f);
    p2 = fmaf(p2, wt, -0.00367342844f);
    p2 = fmaf(p2, wt, 0.00573950773f);
    p2 = fmaf(p2, wt, -0.0076224613f);
    p2 = fmaf(p2, wt, 0.00943887047f);
    p2 = fmaf(p2, wt, 1.00167406f);
    p2 = fmaf(p2, wt, 2.83297682f);
    float p = (w < 5.0f) ? p1 : p2;
    return p * x;
}

// partitionable-mode draw: bits = out0 ^ out1 of cipher(key, (0, idx)).
__device__ __forceinline__ float draw_erfinv(unsigned k0, unsigned k1, unsigned k2,
                                             unsigned idx) {
    unsigned x0 = k0, x1 = idx + k1;
#define TFR(r) { x0 += x1; x1 = __funnelshift_l(x1, x1, r); x1 ^= x0; }
    TFR(13) TFR(15) TFR(26) TFR(6)
    x0 += k1; x1 += k2 + 1u;
    TFR(17) TFR(29) TFR(16) TFR(24)
    x0 += k2; x1 += k0 + 2u;
    TFR(13) TFR(15) TFR(26) TFR(6)
    x0 += k0; x1 += k1 + 3u;
    TFR(17) TFR(29) TFR(16) TFR(24)
    x0 += k1; x1 += k2 + 4u;
    TFR(13) TFR(15) TFR(26) TFR(6)
    x0 += k2; x1 += k0 + 5u;
#undef TFR
    unsigned bits = x0 ^ x1;
    float f = __uint_as_float((bits >> 9) | 0x3f800000u) - 1.0f;  // [0,1)
    const float lo = -0.99999994f;                  // nextafterf(-1,0)
    float v = fmaf(f, 2.0f, lo);                    // (1 - lo) rounds to 2.0f
    return xla_erfinv(v);
}

// -------- packed f32x2 helpers --------
__device__ __forceinline__ unsigned long long pack2(float a, float b) {
    unsigned long long r;
    asm("mov.b64 %0, {%1, %2};" : "=l"(r) : "f"(a), "f"(b));
    return r;
}
__device__ __forceinline__ void unpack2(unsigned long long v, float& a, float& b) {
    asm("mov.b64 {%0, %1}, %2;" : "=f"(a), "=f"(b) : "l"(v));
}
#define FMA2(c, a, bb) asm("fma.rn.f32x2 %0, %1, %2, %0;" : "+l"(c) : "l"(a), "l"(bb))
#define MUL2(o, a, bb) asm("mul.rn.f32x2 %0, %1, %2;" : "=l"(o) : "l"(a), "l"(bb))

// ---------------------------------------------------------------------------
// launch 1: M, mu, xWt
// ---------------------------------------------------------------------------
__global__ void k_setup1(const float* __restrict__ x,
                         const float* __restrict__ We,
                         const float* __restrict__ Wd) {
    int idx = blockIdx.x * 256 + threadIdx.x;
    if (idx < 4096) {
        int i = idx >> 6, j = idx & 63;
        float s = 0.f;
        for (int e = 0; e < 64; e++) s = fmaf(Wd[i * 64 + e], Wd[j * 64 + e], s);
        g_M[idx] = s;
    } else if (idx < 12288) {
        int o = idx - 4096; int b = o >> 6, d = o & 63;
        float sm = 0.f, sw = 0.f;
        for (int e = 0; e < 64; e++) {
            float xe = x[b * 64 + e];
            sm = fmaf(xe, We[e * 64 + d], sm);
            sw = fmaf(xe, Wd[d * 64 + e], sw);
        }
        g_mu[o] = sm; g_xWt[o] = sw;
    }
}

// ---------------------------------------------------------------------------
// launch 2: Jacobi eigensolver (7 sweeps) + cw
// ---------------------------------------------------------------------------
__global__ void __launch_bounds__(1024) k_jac_cw(const float* __restrict__ x) {
    __shared__ float A[64][65];
    __shared__ float Vv[64][65];
    __shared__ float cs[32], sn[32];
    __shared__ int pp[32], qq[32];
    const int t = threadIdx.x;
    for (int o = t; o < 4096; o += 1024) {
        int i = o >> 6, j = o & 63;
        A[i][j] = g_M[o];
        Vv[i][j] = (i == j) ? 1.f : 0.f;
    }
    __syncthreads();
    for (int sweep = 0; sweep < 7; sweep++) {
        for (int r = 0; r < 63; r++) {
            if (t < 32) {
                int p, q;
                if (t == 0) { p = 63; q = r; }
                else { p = (r + t) % 63; q = (r - t + 63) % 63; }
                if (p > q) { int tmp = p; p = q; q = tmp; }
                pp[t] = p; qq[t] = q;
                float apq = A[p][q], app = A[p][p], aqq = A[q][q];
                float c = 1.f, s = 0.f;
                if (fabsf(apq) > 1e-30f) {
                    float tau = (aqq - app) / (2.f * apq);
                    float tt = ((tau >= 0.f) ? 1.f : -1.f) /
                               (fabsf(tau) + sqrtf(1.f + tau * tau));
                    c = rsqrtf(1.f + tt * tt);
                    s = tt * c;
                }
                cs[t] = c; sn[t] = s;
            }
            __syncthreads();
            for (int u = t; u < 2048; u += 1024) {
                int m = u >> 6, j = u & 63;
                int p = pp[m], q = qq[m];
                float c = cs[m], s = sn[m];
                float ap = A[p][j], aq = A[q][j];
                A[p][j] = c * ap - s * aq;
                A[q][j] = s * ap + c * aq;
            }
            __syncthreads();
            for (int u = t; u < 2048; u += 1024) {
                int m = u >> 6, i = u & 63;
                int p = pp[m], q = qq[m];
                float c = cs[m], s = sn[m];
                float ap = A[i][p], aq = A[i][q];
                A[i][p] = c * ap - s * aq;
                A[i][q] = s * ap + c * aq;
                float vp = Vv[i][p], vq = Vv[i][q];
                Vv[i][p] = c * vp - s * vq;
                Vv[i][q] = s * vp + c * vq;
            }
            __syncthreads();
        }
    }
    for (int o = t; o < 4096; o += 1024) g_V[o] = Vv[o >> 6][o & 63];
    if (t < 64) g_lam[t] = A[t][t];
    if (t < 128) {   // const_b = 0.5||mu||^2 - 0.5||x||^2 - 32 log 2pi
        float s = 0.f, sx = 0.f;
        for (int d = 0; d < 64; d++) {
            float m = g_mu[t * 64 + d]; s = fmaf(m, m, s);
            float xe = x[t * 64 + d];   sx = fmaf(xe, xe, sx);
        }
        g_cw[t] = 0.5f * s - 0.5f * sx - 58.81206612509905f;
    }
}

// ---------------------------------------------------------------------------
// launch 3: eigenbasis transform + per-step coefficients + drift, fused
// ---------------------------------------------------------------------------
__global__ void k_transcoef(Params prm) {
    int o = blockIdx.x * 256 + threadIdx.x;   // 8192 = (b, i)
    int b = o >> 6, i = o & 63;
    float sm = 0.f, sx = 0.f;
    for (int d = 0; d < 64; d++) {
        float v = g_V[d * 64 + i];
        sm = fmaf(g_mu[b * 64 + d], v, sm);
        sx = fmaf(g_xWt[b * 64 + d], v, sx);
    }
    g_mtT[i * 128 + b] = sm;
    g_uT[i * 128 + b] = sx - sm;
    const float h = 0.05f, h2 = 0.0025f;
    float lam = g_lam[i];
    for (int k = 0; k < 16; k++) {
        float bk = prm.beta[k + 1];
        float c = h2 * (bk * lam + 1.f);
        float sd = h2 * (4.5f - 3.f * c + 0.5f * c * c);
        float vt = bk * sx + (1.f - bk) * sm;
        g_dT[(k * 64 + i) * 128 + b] = sd * vt;
        if (b == 0) {
            g_pc[k * 64 + i] = 1.f - 4.5f * c + 3.f * c * c - 0.5f * c * c * c;
            g_qd[k * 64 + i] = 1.41421356237f * h * (3.f - 4.f * c + c * c);
        }
    }
}

// ---------------------------------------------------------------------------
// launch 4: k_eps — stateless over (chain, step). 64 draws -> eps~ via
// sVq = V*qd(k), add drift, store paired: g_eps2[(k*32+j)][chain].
// __launch_bounds__(128,5): force <=102 regs for 20 warps/SM.
// ---------------------------------------------------------------------------
__global__ void __launch_bounds__(128, 5) k_eps(Params prm) {
    __shared__ float sVq[4096];               // [d][i] = V[d][i] * qd[k][i]
    const int k  = blockIdx.x >> 10;
    const int cb = blockIdx.x & 1023;
    const int t  = threadIdx.x;
    const unsigned chain = (unsigned)cb * 128u + (unsigned)t;
    for (int o = t; o < 4096; o += 128)
        sVq[o] = g_V[o] * g_qd[k * 64 + (o & 63)];
    __syncthreads();

    const unsigned fk0 = prm.fk0[k], fk1 = prm.fk1[k];
    const unsigned fk2 = fk0 ^ fk1 ^ 0x1BD11BDAu;
    const unsigned base = chain * 64u;
    unsigned long long acc[32];
#pragma unroll
    for (int j = 0; j < 32; j++) acc[j] = 0ull;

#pragma unroll 2
    for (int d = 0; d < 64; d++) {
        float e = draw_erfinv(fk0, fk1, fk2, base + (unsigned)d);
        unsigned long long pe = pack2(e, e);
        const ulonglong2* row = (const ulonglong2*)(sVq + d * 64);
#pragma unroll
        for (int j = 0; j < 16; j++) {
            ulonglong2 w = row[j];
            FMA2(acc[2 * j],     pe, w.x);
            FMA2(acc[2 * j + 1], pe, w.y);
        }
    }
    const float* dTk = g_dT + k * 8192 + t;             // + i*128
    unsigned long long* op = g_eps2 + (((size_t)k * 32) << 17) + chain;
#pragma unroll
    for (int j = 0; j < 32; j++) {
        float a0, a1;
        unpack2(acc[j], a0, a1);
        a0 += dTk[(2 * j) * 128];
        a1 += dTk[(2 * j + 1) * 128];
        op[(size_t)j << 17] = pack2(a0, a1);
    }
}

// ---------------------------------------------------------------------------
// launch 5: k_main — per-chain elementwise recursion + weights (all f32x2).
// 128 threads/block: b == t, n == blockIdx.x.
// dyn smem: sU2 32KB | sV 16KB | sPc 4KB | sLam2 256B  (52.25KB)
// ---------------------------------------------------------------------------
__global__ void __launch_bounds__(128) k_main(const float* __restrict__ qn,
                                              Params prm) {
    extern __shared__ float dsm[];
    unsigned long long* sU2   = (unsigned long long*)dsm;            // [j][b] 32*128
    float*              sV    = dsm + 8192;                          // 4096
    float*              sPc   = dsm + 12288;                         // 1024
    unsigned long long* sLam2 = (unsigned long long*)(dsm + 13312);  // 32
    const int t = threadIdx.x;
    const unsigned chain = (unsigned)blockIdx.x * 128u + (unsigned)t;
    const int b = t;
    const int n = blockIdx.x;

    for (int j = 0; j < 32; j++)   // pack u pairs
        sU2[j * 128 + t] = pack2(g_uT[(2 * j) * 128 + t], g_uT[(2 * j + 1) * 128 + t]);
    for (int o = t; o < 4096; o += 128) sV[o] = g_V[o];
    for (int o = t; o < 1024; o += 128) sPc[o] = g_pc[o];
    if (t < 32) sLam2[t] = pack2(g_lam[2 * t], g_lam[2 * t + 1]);
    __syncthreads();

    // q~0 = mu~ + (qn V)   (paired accumulators)
    float qreg[64];
    const float4* qp = (const float4*)(qn + (size_t)chain * 64u);
#pragma unroll
    for (int j = 0; j < 16; j++) {
        float4 v = qp[j];
        qreg[4 * j] = v.x; qreg[4 * j + 1] = v.y;
        qreg[4 * j + 2] = v.z; qreg[4 * j + 3] = v.w;
    }
    unsigned long long q2[32];
#pragma unroll
    for (int j = 0; j < 32; j++) q2[j] = 0ull;
#pragma unroll 4
    for (int d = 0; d < 64; d++) {
        unsigned long long pe = pack2(qreg[d], qreg[d]);
        const ulonglong2* row = (const ulonglong2*)(sV + d * 64);
#pragma unroll
        for (int j = 0; j < 16; j++) {
            ulonglong2 w = row[j];
            FMA2(q2[2 * j],     pe, w.x);
            FMA2(q2[2 * j + 1], pe, w.y);
        }
    }
#pragma unroll
    for (int j = 0; j < 32; j++) {
        float a0, a1;
        unpack2(q2[j], a0, a1);
        q2[j] = pack2(a0 + g_mtT[(2 * j) * 128 + b],
                      a1 + g_mtT[(2 * j + 1) * 128 + b]);
    }

    const float cw = g_cw[b];
    float slw;
    {
        unsigned long long dacc = 0ull, qacc = 0ull;
#pragma unroll
        for (int j = 0; j < 32; j++) {
            FMA2(dacc, q2[j], sU2[j * 128 + b]);
            unsigned long long lq;
            MUL2(lq, sLam2[j], q2[j]);
            FMA2(qacc, lq, q2[j]);
        }
        float d0, d1, s0, s1;
        unpack2(dacc, d0, d1); unpack2(qacc, s0, s1);
        float w = cw + (d0 + d1) - 0.5f * (s0 + s1);
        slw = (prm.beta[1] - prm.beta[0]) * w;
    }

    for (int k = 0; k < 16; k++) {
        const unsigned long long* ep = g_eps2 + (((size_t)k * 32) << 17) + chain;
        const unsigned long long* pc2 = (const unsigned long long*)(sPc + k * 64);
#pragma unroll
        for (int j = 0; j < 32; j++) {
            unsigned long long e = __ldg(ep + ((size_t)j << 17));
            FMA2(e, pc2[j], q2[j]);      // e += pc * q
            q2[j] = e;
        }
        unsigned long long dacc = 0ull, qacc = 0ull;
#pragma unroll
        for (int j = 0; j < 32; j++) {
            FMA2(dacc, q2[j], sU2[j * 128 + b]);
            unsigned long long lq;
            MUL2(lq, sLam2[j], q2[j]);
            FMA2(qacc, lq, q2[j]);
        }
        float d0, d1, s0, s1;
        unpack2(dacc, d0, d1); unpack2(qacc, s0, s1);
        float w = cw + (d0 + d1) - 0.5f * (s0 + s1);
        slw = fmaf(prm.beta[k + 2] - prm.beta[k + 1], w, slw);
    }
    g_slw[b * 1024 + n] = slw;
}

// ---------------------------------------------------------------------------
// launch 6: logsumexp over n, minus log(1024)
// ---------------------------------------------------------------------------
__global__ void k_reduce(float* __restrict__ out) {
    const int b = blockIdx.x;
    const int t = threadIdx.x;          // 128
    __shared__ float red[128];
    float m = -3.4e38f;
    for (int i = t; i < 1024; i += 128) m = fmaxf(m, g_slw[b * 1024 + i]);
    red[t] = m; __syncthreads();
    for (int s = 64; s > 0; s >>= 1) {
        if (t < s) red[t] = fmaxf(red[t], red[t + s]);
        __syncthreads();
    }
    float mx = red[0]; __syncthreads();
    float acc = 0.f;
    for (int i = t; i < 1024; i += 128) acc += expf(g_slw[b * 1024 + i] - mx);
    red[t] = acc; __syncthreads();
    for (int s = 64; s > 0; s >>= 1) {
        if (t < s) red[t] += red[t + s];
        __syncthreads();
    }
    if (t == 0) out[b] = mx + logf(red[0]) - 6.9314718055994531f;  // log(1024)
}

// ---------------------------------------------------------------------------
extern "C" void kernel_launch(void* const* d_in, const int* in_sizes, int n_in,
                              void* d_out, int out_size) {
    const float* x    = (const float*)d_in[0];
    const float* Wenc = (const float*)d_in[1];
    const float* Wdec = (const float*)d_in[2];
    const float* qn   = (const float*)d_in[3];
    // d_in[4] = p_noise — unused (momentum fully resampled each step)
    float* out = (float*)d_out;

    Params prm;
    double bb[18];
    for (int i = 0; i < 18; i++) {
        double z = 4.0 * (2.0 * ((double)i / 17.0) - 1.0);
        bb[i] = 1.0 / (1.0 + exp(-z));
    }
    for (int i = 0; i < 18; i++)
        prm.beta[i] = (float)((bb[i] - bb[0]) / (bb[17] - bb[0]));
    for (int k = 1; k <= 16; k++) {
        unsigned o0, o1;
        tf2x32(0u, 42u, 0u, (unsigned)k, &o0, &o1);   // fold_in(key(42), k)
        prm.fk0[k - 1] = o0; prm.fk1[k - 1] = o1;
    }

    cudaFuncSetAttribute(k_main, cudaFuncAttributeMaxDynamicSharedMemorySize, 53504);

    k_setup1<<<48, 256>>>(x, Wenc, Wdec);
    k_jac_cw<<<1, 1024>>>(x);
    k_transcoef<<<32, 256>>>(prm);
    k_eps<<<16384, 128>>>(prm);
    k_main<<<1024, 128, 53504>>>(qn, prm);
    k_reduce<<<128, 128>>>(out);
}